// round 15
// baseline (speedup 1.0000x reference)
#include <cuda_runtime.h>
#include <cuda_bf16.h>
#include <stdint.h>
#include <math.h>

#define BB 16
#define NN 64
#define DD 4
#define TT 40
#define LL 10
#define HH 128
#define KK 4
#define EE (NN*(NN-1))

// fp32 tile: 128 x 132 words
#define SPW  132
#define TILEF_B (128*SPW*4)   // 67584
#define UVH_B  (64*SPW*4)     // 33792 (half B tile)
// bf16 tile (msg): 128 x 136 halves (272 B/row)
#define SP   136
#define SPB  272
#define TILEH_B (128*SPB)     // 34816

// ---------------- persistent device state ----------------
__device__ float g_hidden[BB*NN*HH];
__device__ float g_pred[BB*NN*DD];
__device__ __align__(16) __nv_bfloat16 g_uv[BB*8*NN*HH];  // [B][ks][N][H] bf16
__device__ float g_aggk[KK*BB*NN*HH];                     // per-k partial aggregates
__device__ __align__(16) float g_W1T[8*128*SPW];          // fp32 [ks][128][132]
__device__ __align__(16) __nv_bfloat16 g_W2T[4*128*SP];   // bf16 [k][128][136]
__device__ __align__(16) float g_WnT[5*128*SPW];          // node weights^T padded [m][h][132]

// ---------------- PTX helpers ----------------
__device__ __forceinline__ uint32_t smem_u32(const void* p) {
    uint32_t a;
    asm("{ .reg .u64 t; cvta.to.shared.u64 t, %1; cvt.u32.u64 %0, t; }" : "=r"(a) : "l"(p));
    return a;
}
#define MBAR_INIT(mb, c)  asm volatile("mbarrier.init.shared.b64 [%0], %1;" :: "r"(mb), "r"(c) : "memory")
#define MBAR_EXPECT_TX(mb, n) asm volatile("mbarrier.arrive.expect_tx.shared.b64 _, [%0], %1;" :: "r"(mb), "r"(n) : "memory")
#define FENCE_ASYNC()     asm volatile("fence.proxy.async.shared::cta;" ::: "memory")
#define BULK_CP(dst, src, bytes, mb) \
    asm volatile("cp.async.bulk.shared::cta.global.mbarrier::complete_tx::bytes [%0], [%1], %2, [%3];" \
        :: "r"(dst), "l"(src), "r"(bytes), "r"(mb) : "memory")

#define MBAR_WAIT(mb, ph) do { \
    uint32_t _m = (mb); uint32_t _p = (ph); uint32_t _d; \
    asm volatile("{\n\t.reg .pred p;\n\tmbarrier.try_wait.parity.acquire.cta.shared::cta.b64 p, [%1], %2;\n\tselp.b32 %0, 1, 0, p;\n\t}" \
        : "=r"(_d) : "r"(_m), "r"(_p) : "memory"); \
    if (!_d) { \
        asm volatile("{\n\t.reg .pred P1;\n\tWL_%=:\n\tmbarrier.try_wait.parity.acquire.cta.shared::cta.b64 P1, [%0], %1, 0x989680;\n\t@P1 bra.uni WD_%=;\n\tbra.uni WL_%=;\n\tWD_%=:\n\t}" \
            :: "r"(_m), "r"(_p) : "memory"); \
    } \
} while (0)

// tf32 mma m16n8k8
__device__ __forceinline__ void mma_tf32(float d[4], uint32_t a0, uint32_t a1, uint32_t a2, uint32_t a3,
                                         uint32_t b0, uint32_t b1) {
    asm volatile("mma.sync.aligned.m16n8k8.row.col.f32.tf32.tf32.f32 "
        "{%0,%1,%2,%3}, {%4,%5,%6,%7}, {%8,%9}, {%0,%1,%2,%3};"
        : "+f"(d[0]), "+f"(d[1]), "+f"(d[2]), "+f"(d[3])
        : "r"(a0), "r"(a1), "r"(a2), "r"(a3), "r"(b0), "r"(b1));
}
// bf16 mma m16n8k16
__device__ __forceinline__ void mma_bf16(float d[4], uint32_t a0, uint32_t a1, uint32_t a2, uint32_t a3,
                                         uint32_t b0, uint32_t b1) {
    asm volatile("mma.sync.aligned.m16n8k16.row.col.f32.bf16.bf16.f32 "
        "{%0,%1,%2,%3}, {%4,%5,%6,%7}, {%8,%9}, {%0,%1,%2,%3};"
        : "+f"(d[0]), "+f"(d[1]), "+f"(d[2]), "+f"(d[3])
        : "r"(a0), "r"(a1), "r"(a2), "r"(a3), "r"(b0), "r"(b1));
}
__device__ __forceinline__ void ldsm_x4(uint32_t& r0, uint32_t& r1, uint32_t& r2, uint32_t& r3, uint32_t addr) {
    asm volatile("ldmatrix.sync.aligned.m8n8.x4.shared.b16 {%0,%1,%2,%3}, [%4];"
        : "=r"(r0), "=r"(r1), "=r"(r2), "=r"(r3) : "r"(addr));
}

// tf32 GEMM (uv): 16 warps, warp tile 16m x 32n (M=128, N=64 per block)
__device__ __forceinline__ void gemm_tf32_16(const float* __restrict__ A, const float* __restrict__ B,
                                             float acc[4][4], int mblk, int nblk, int lane) {
    int gid = lane >> 2, tig = lane & 3;
    const float* ap0 = A + (mblk * 16 + gid) * SPW + tig;
    const float* bp0 = B + (nblk * 32 + gid) * SPW + tig;
    #pragma unroll
    for (int ks = 0; ks < 16; ks++) {
        int k0 = ks * 8;
        uint32_t a0 = __float_as_uint(ap0[k0]);
        uint32_t a1 = __float_as_uint(ap0[8 * SPW + k0]);
        uint32_t a2 = __float_as_uint(ap0[k0 + 4]);
        uint32_t a3 = __float_as_uint(ap0[8 * SPW + k0 + 4]);
        #pragma unroll
        for (int nf = 0; nf < 4; nf++) {
            const float* bp = bp0 + nf * 8 * SPW + k0;
            uint32_t b0 = __float_as_uint(bp[0]);
            uint32_t b1 = __float_as_uint(bp[4]);
            mma_tf32(acc[nf], a0, a1, a2, a3, b0, b1);
        }
    }
}

// bf16 GEMM via ldmatrix: warp tile 32m x 32n
__device__ __forceinline__ void gemm_bf16_ldsm(uint32_t smA, uint32_t smB,
                                               float acc[2][4][4], int mblk, int nblk, int lane) {
    uint32_t aB0 = smA + (uint32_t)(mblk * 32 + (lane & 15)) * SPB + (uint32_t)(lane >> 4) * 16;
    uint32_t aB1 = aB0 + 16 * SPB;
    uint32_t bB0 = smB + (uint32_t)(nblk * 32 + ((lane >> 4) << 3) + (lane & 7)) * SPB
                 + (uint32_t)((lane >> 3) & 1) * 16;
    uint32_t bB1 = bB0 + 16 * SPB;
    #pragma unroll
    for (int ks = 0; ks < 8; ks++) {
        uint32_t kb = (uint32_t)ks * 32;
        uint32_t a0[4], a1[4], b0[4], b1[4];
        ldsm_x4(a0[0], a0[1], a0[2], a0[3], aB0 + kb);
        ldsm_x4(a1[0], a1[1], a1[2], a1[3], aB1 + kb);
        ldsm_x4(b0[0], b0[1], b0[2], b0[3], bB0 + kb);
        ldsm_x4(b1[0], b1[1], b1[2], b1[3], bB1 + kb);
        mma_bf16(acc[0][0], a0[0], a0[1], a0[2], a0[3], b0[0], b0[1]);
        mma_bf16(acc[1][0], a1[0], a1[1], a1[2], a1[3], b0[0], b0[1]);
        mma_bf16(acc[0][1], a0[0], a0[1], a0[2], a0[3], b0[2], b0[3]);
        mma_bf16(acc[1][1], a1[0], a1[1], a1[2], a1[3], b0[2], b0[3]);
        mma_bf16(acc[0][2], a0[0], a0[1], a0[2], a0[3], b1[0], b1[1]);
        mma_bf16(acc[1][2], a1[0], a1[1], a1[2], a1[3], b1[0], b1[1]);
        mma_bf16(acc[0][3], a0[0], a0[1], a0[2], a0[3], b1[2], b1[3]);
        mma_bf16(acc[1][3], a1[0], a1[1], a1[2], a1[3], b1[2], b1[3]);
    }
}

// ---------------- fast math ----------------
__device__ __forceinline__ float fex2_(float x) { float r; asm("ex2.approx.f32 %0, %1;" : "=f"(r) : "f"(x)); return r; }
__device__ __forceinline__ float frcp_(float x) { float r; asm("rcp.approx.f32 %0, %1;" : "=f"(r) : "f"(x)); return r; }
__device__ __forceinline__ float ftanh_(float x) { return fmaf(-2.0f, frcp_(fex2_(x * 2.885390081777927f) + 1.0f), 1.0f); }
__device__ __forceinline__ float fsig_(float x)  { return frcp_(1.0f + fex2_(-1.4426950408889634f * x)); }
__device__ __forceinline__ float ftanha_(float x){ float r; asm("tanh.approx.f32 %0, %1;" : "=f"(r) : "f"(x)); return r; }

// ---------------- init ----------------
__global__ void init_kernel() {
    int i = blockIdx.x * blockDim.x + threadIdx.x;
    if (i < BB*NN*HH) g_hidden[i] = 0.0f;
    if (i < BB*NN*DD) g_pred[i]   = 0.0f;
}

// ---------------- prep ----------------
__global__ __launch_bounds__(256)
void prep_kernel(const float* __restrict__ W1, const float* __restrict__ W2,
                 const float* __restrict__ Wr_h, const float* __restrict__ Wi_h,
                 const float* __restrict__ Wh_h, const float* __restrict__ Wo1,
                 const float* __restrict__ Wo2) {
    int s = blockIdx.x;
    if (s < 8) {
        const float* src = W1 + s * 16384;
        float* dst = g_W1T + s * 128 * SPW;
        for (int t = threadIdx.x; t < 16384; t += 256) {
            int n = t >> 7, f = t & 127;
            dst[n * SPW + f] = src[f * 128 + n];
        }
    } else if (s < 12) {
        const float* src = W2 + (s - 8) * 16384;
        __nv_bfloat16* dst = g_W2T + (s - 8) * 128 * SP;
        for (int t = threadIdx.x; t < 16384; t += 256) {
            int n = t >> 7, f = t & 127;
            dst[n * SP + f] = __float2bfloat16_rn(src[f * 128 + n]);
        }
    } else {
        const float* src;
        switch (s - 12) {
            case 0: src = Wr_h; break;
            case 1: src = Wi_h; break;
            case 2: src = Wh_h; break;
            case 3: src = Wo1;  break;
            default: src = Wo2; break;
        }
        float* dst = g_WnT + (s - 12) * 128 * SPW;
        for (int t = threadIdx.x; t < 16384; t += 256) {
            int h = t >> 7, f = t & 127;
            dst[h * SPW + f] = src[f * 128 + h];
        }
    }
}

// ---------------- UV: tf32 GEMM (n-split x2), bf16 output ----------------
#define UV_A  0
#define UV_B  TILEF_B
#define UV_MB (TILEF_B + UVH_B)
#define UV_SMEM (UV_MB + 32)

__global__ __launch_bounds__(512)
void uv_kernel() {
    extern __shared__ char sm[];
    uint32_t smb = smem_u32(sm);
    int tid = threadIdx.x;
    int ks = blockIdx.x >> 1, nh = blockIdx.x & 1;
    int bp = blockIdx.y;
    uint32_t mbt = smb + UV_MB;
    float* A = (float*)(sm + UV_A);
    const float* Bt = (const float*)(sm + UV_B);

    if (tid == 0) {
        MBAR_INIT(mbt, 1);
        FENCE_ASYNC();
        MBAR_EXPECT_TX(mbt, UVH_B);
        BULK_CP(smb + UV_B, (const char*)(g_W1T + (size_t)ks * 128 * SPW + (size_t)nh * 64 * SPW), UVH_B, mbt);
    }
    for (int idx = tid; idx < 128 * 32; idx += 512) {
        int row = idx >> 5, f4 = (idx & 31) * 4;
        int b = bp * 2 + (row >> 6), node = row & 63;
        float4 v = *(const float4*)(g_hidden + ((size_t)(b * NN + node)) * HH + f4);
        *(float4*)&A[row * SPW + f4] = v;
    }
    __syncthreads();
    MBAR_WAIT(mbt, 0);

    int w = tid >> 5, lane = tid & 31;
    int mblk = w & 7, nblk = w >> 3;   // 8 x 2 warps, tile 16m x 32n
    int gid = lane >> 2, tig = lane & 3;

    float acc[4][4];
    #pragma unroll
    for (int nf = 0; nf < 4; nf++)
        #pragma unroll
        for (int j = 0; j < 4; j++) acc[nf][j] = 0.0f;

    gemm_tf32_16(A, Bt, acc, mblk, nblk, lane);
    __syncthreads();   // done reading A; reuse as staging (128 x 64 cols)

    {
        int r0 = mblk * 16 + gid;
        #pragma unroll
        for (int nf = 0; nf < 4; nf++) {
            int c = nblk * 32 + nf * 8 + tig * 2;
            *(float2*)&A[r0 * SPW + c]       = make_float2(acc[nf][0], acc[nf][1]);
            *(float2*)&A[(r0 + 8) * SPW + c] = make_float2(acc[nf][2], acc[nf][3]);
        }
    }
    __syncthreads();
    for (int idx = tid; idx < 128 * 8; idx += 512) {
        int row = idx >> 3, c8 = (idx & 7) * 8;
        float4 v0 = *(const float4*)&A[row * SPW + c8];
        float4 v1 = *(const float4*)&A[row * SPW + c8 + 4];
        __nv_bfloat162 p0 = __floats2bfloat162_rn(v0.x, v0.y);
        __nv_bfloat162 p1 = __floats2bfloat162_rn(v0.z, v0.w);
        __nv_bfloat162 p2 = __floats2bfloat162_rn(v1.x, v1.y);
        __nv_bfloat162 p3 = __floats2bfloat162_rn(v1.z, v1.w);
        int b = bp * 2 + (row >> 6), node = row & 63;
        __nv_bfloat162* dst = (__nv_bfloat162*)(g_uv + ((size_t)(b * 8 + ks) * 64 + node) * 128 + nh * 64 + c8);
        dst[0] = p0; dst[1] = p1; dst[2] = p2; dst[3] = p3;
    }
}

// ---------------- MSG kernel: one block per (pair, batch, k); 2 CTAs/SM ----------------
#define MS_A    0
#define MS_B    34816
#define MS_U    69632
#define MS_VS   86016
#define MS_SCR  87040
#define MS_REL  89088
#define MS_SEND 89600
#define MS_B2   90112
#define MS_MB   90624
#define MSG_SMEM 90656

__global__ __launch_bounds__(512, 2)
void msg_kernel(const float* __restrict__ b1, const float* __restrict__ b2,
                const float* __restrict__ rel,
                const int* __restrict__ recv_idx, const int* __restrict__ send_idx) {
    extern __shared__ char sm[];
    uint32_t smb = smem_u32(sm);
    int tid = threadIdx.x;
    int p = blockIdx.x, b = blockIdx.y, k = blockIdx.z;

    float* RelS  = (float*)(sm + MS_REL);
    int*   SendS = (int*)(sm + MS_SEND);
    float* b2S   = (float*)(sm + MS_B2);
    float* vS    = (float*)(sm + MS_VS);
    float* scr   = (float*)(sm + MS_SCR);
    uint32_t bbar = smb + MS_MB, ubar = smb + MS_MB + 8;

    if (tid == 0) {
        MBAR_INIT(bbar, 1);
        MBAR_INIT(ubar, 1);
        FENCE_ASYNC();
        MBAR_EXPECT_TX(bbar, TILEH_B);
        BULK_CP(smb + MS_B, (const char*)(g_W2T + (size_t)k * 128 * SP), TILEH_B, bbar);
        MBAR_EXPECT_TX(ubar, 16384);
        BULK_CP(smb + MS_U, (const char*)(g_uv + (size_t)(b * 8 + 2 * k) * 8192), 16384, ubar);
    }
    int r0n = recv_idx[p * 126];
    int r1n = recv_idx[p * 126 + 63];
    if (tid < 128) {
        int row = tid;
        float rw = 0.0f;
        int sn = 0;
        if (row != 63 && row != 127) {
            int e = (row < 64) ? (p * 126 + row) : (p * 126 + row - 1);
            sn = send_idx[e];
            rw = rel[((size_t)(b * EE + e)) * KK + k];
        }
        SendS[row] = sn;
        RelS[row] = rw;
        b2S[row] = b2[k * 128 + row];
    } else if (tid < 384) {
        int f = tid & 127, rh = (tid >> 7) & 1;
        int rv = rh ? r1n : r0n;
        const __nv_bfloat16* v = g_uv + ((size_t)(b * 8 + 2 * k + 1)) * 8192 + rv * 128;
        vS[rh * 128 + f] = __bfloat162float(v[f]) + b1[k * 128 + f];
    }
    __syncthreads();   // mbarrier init + vS/metadata visible

    // build A = bf16(tanh(u[send] + vS)); rows 63/127 zero.
    MBAR_WAIT(ubar, 0);
    {
        const __nv_bfloat16* U = (const __nv_bfloat16*)(sm + MS_U);
        int f4 = (tid & 31) * 4;
        int rowbase = tid >> 5;
        float4 vv0 = *(const float4*)&vS[f4];
        float4 vv1 = *(const float4*)&vS[128 + f4];
        char* Abase = sm + MS_A + f4 * 2;
        #pragma unroll
        for (int it = 0; it < 8; it++) {
            int row = rowbase + 16 * it;
            uint32_t o01 = 0, o23 = 0;
            if (row != 63 && row != 127) {
                int sn = SendS[row];
                float4 vv = (row < 64) ? vv0 : vv1;
                uint2 q = *(const uint2*)(U + sn * 128 + f4);
                float2 f0 = __bfloat1622float2(*(__nv_bfloat162*)&q.x);
                float2 f1 = __bfloat1622float2(*(__nv_bfloat162*)&q.y);
                __nv_bfloat162 p0 = __floats2bfloat162_rn(ftanha_(f0.x + vv.x), ftanha_(f0.y + vv.y));
                __nv_bfloat162 p1 = __floats2bfloat162_rn(ftanha_(f1.x + vv.z), ftanha_(f1.y + vv.w));
                o01 = *(uint32_t*)&p0; o23 = *(uint32_t*)&p1;
            }
            *(uint2*)(Abase + row * SPB) = make_uint2(o01, o23);
        }
    }
    __syncthreads();

    MBAR_WAIT(bbar, 0);
    int w = tid >> 5, lane = tid & 31;
    int mblk = w & 3, nblk = w >> 2;
    int gid = lane >> 2, tig = lane & 3;

    float acc[2][4][4];
    #pragma unroll
    for (int mf = 0; mf < 2; mf++)
        #pragma unroll
        for (int nf = 0; nf < 4; nf++)
            #pragma unroll
            for (int j = 0; j < 4; j++) acc[mf][nf][j] = 0.0f;

    gemm_bf16_ldsm(smb + MS_A, smb + MS_B, acc, mblk, nblk, lane);

    // fused epilogue + row-sum
    float sum[4][2];
    #pragma unroll
    for (int nf = 0; nf < 4; nf++) { sum[nf][0] = 0.0f; sum[nf][1] = 0.0f; }
    {
        int r0 = mblk * 32 + gid;
        float rw0 = RelS[r0];
        float rw1 = RelS[r0 + 8];
        float rw2 = RelS[r0 + 16];
        float rw3 = RelS[r0 + 24];
        #pragma unroll
        for (int nf = 0; nf < 4; nf++) {
            int c = nblk * 32 + nf * 8 + tig * 2;
            float bb0 = b2S[c], bb1 = b2S[c + 1];
            sum[nf][0] += rw0 * ftanha_(acc[0][nf][0] + bb0)
                        + rw1 * ftanha_(acc[0][nf][2] + bb0)
                        + rw2 * ftanha_(acc[1][nf][0] + bb0)
                        + rw3 * ftanha_(acc[1][nf][2] + bb0);
            sum[nf][1] += rw0 * ftanha_(acc[0][nf][1] + bb1)
                        + rw1 * ftanha_(acc[0][nf][3] + bb1)
                        + rw2 * ftanha_(acc[1][nf][1] + bb1)
                        + rw3 * ftanha_(acc[1][nf][3] + bb1);
        }
    }
    #pragma unroll
    for (int off = 16; off >= 4; off >>= 1)
        #pragma unroll
        for (int nf = 0; nf < 4; nf++) {
            sum[nf][0] += __shfl_down_sync(0xffffffffu, sum[nf][0], off);
            sum[nf][1] += __shfl_down_sync(0xffffffffu, sum[nf][1], off);
        }
    if (gid == 0) {
        #pragma unroll
        for (int nf = 0; nf < 4; nf++) {
            int c = nblk * 32 + nf * 8 + tig * 2;
            *(float2*)&scr[mblk * 128 + c] = make_float2(sum[nf][0], sum[nf][1]);
        }
    }
    __syncthreads();
    if (tid < 256) {
        int h = tid & 127, rh = tid >> 7;
        float a = scr[(rh * 2) * 128 + h] + scr[(rh * 2 + 1) * 128 + h];
        int rv = rh ? r1n : r0n;
        g_aggk[(((size_t)k * BB + b) * NN + rv) * HH + h] = a;
    }
}

// ---------------- NODE kernel: 512 threads, 16 nodes/block, 64 blocks ----------------
#define ND_WB0 0
#define ND_WB1 67584
#define ND_AGG 135168
#define ND_HID 143360
#define ND_T1  151552
#define ND_T2  159744
#define ND_INS 167936
#define ND_WIN 168192
#define ND_BIA 174336
#define ND_WO3 176896
#define ND_BO3 178944
#define ND_MB  178960
#define NODE_SMEM 179024

__global__ __launch_bounds__(512)
void node_kernel(const float* __restrict__ data, int step,
                 const float* __restrict__ Wr_in, const float* __restrict__ br_in,
                 const float* __restrict__ Wi_in, const float* __restrict__ bi_in,
                 const float* __restrict__ Wn_in, const float* __restrict__ bn_in,
                 const float* __restrict__ bo1, const float* __restrict__ bo2,
                 const float* __restrict__ Wo3, const float* __restrict__ bo3,
                 float* __restrict__ out) {
    extern __shared__ char sm[];
    uint32_t smb = smem_u32(sm);
    int q = blockIdx.x, b = blockIdx.y;
    int n0 = q * 16;
    int tid = threadIdx.x;

    float* aggS = (float*)(sm + ND_AGG);
    float* hidS = (float*)(sm + ND_HID);
    float* t1   = (float*)(sm + ND_T1);
    float* t2   = (float*)(sm + ND_T2);
    float* insS = (float*)(sm + ND_INS);
    float* WinS = (float*)(sm + ND_WIN);
    float* biaS = (float*)(sm + ND_BIA);
    float* Wo3S = (float*)(sm + ND_WO3);
    float* bo3S = (float*)(sm + ND_BO3);
    uint32_t mb0 = smb + ND_MB, mb1 = smb + ND_MB + 8;

    if (tid == 0) {
        MBAR_INIT(mb0, 1);
        MBAR_INIT(mb1, 1);
        FENCE_ASYNC();
        MBAR_EXPECT_TX(mb0, TILEF_B);
        BULK_CP(smb + ND_WB0, (const char*)(g_WnT + 0), TILEF_B, mb0);
        MBAR_EXPECT_TX(mb1, TILEF_B);
        BULK_CP(smb + ND_WB1, (const char*)(g_WnT + (size_t)1 * 128 * SPW), TILEF_B, mb1);
    }
    {
        size_t base = ((size_t)(b * NN + n0)) * HH;
        const float4* a0 = (const float4*)(g_aggk + base);
        const float4* a1 = (const float4*)(g_aggk + base + (size_t)BB * NN * HH);
        const float4* a2 = (const float4*)(g_aggk + base + (size_t)2 * BB * NN * HH);
        const float4* a3 = (const float4*)(g_aggk + base + (size_t)3 * BB * NN * HH);
        float4 s0 = a0[tid], s1 = a1[tid], s2 = a2[tid], s3 = a3[tid];
        float4 s;
        s.x = (s0.x + s1.x + s2.x + s3.x) * (1.0f / 16.0f);
        s.y = (s0.y + s1.y + s2.y + s3.y) * (1.0f / 16.0f);
        s.z = (s0.z + s1.z + s2.z + s3.z) * (1.0f / 16.0f);
        s.w = (s0.w + s1.w + s2.w + s3.w) * (1.0f / 16.0f);
        ((float4*)aggS)[tid] = s;
        const float* hg = g_hidden + base;
        ((float4*)hidS)[tid] = ((const float4*)hg)[tid];
    }
    if (tid < 64) {
        int n = tid >> 2, d = tid & 3;
        float v;
        if (step < TT) v = data[(((size_t)(b * NN + n0 + n)) * DD + d) * TT + step];
        else           v = g_pred[(b * NN + n0 + n) * DD + d];
        insS[tid] = v;
    }
    if (tid < 512) {
        WinS[tid]        = Wr_in[tid];
        WinS[512 + tid]  = Wi_in[tid];
        WinS[1024 + tid] = Wn_in[tid];
        Wo3S[tid]        = Wo3[tid];
    }
    if (tid < 128) {
        biaS[tid]       = br_in[tid];
        biaS[128 + tid] = bi_in[tid];
        biaS[256 + tid] = bn_in[tid];
        biaS[384 + tid] = bo1[tid];
        biaS[512 + tid] = bo2[tid];
    }
    if (tid < 4) bo3S[tid] = bo3[tid];
    __syncthreads();

    int h = tid & 127, ng = (tid >> 7) * 4;   // 4 groups of 4 nodes = 16

    #define GEMV4(ACT, WB, OUTARR) do { \
        const float4* _wt = (const float4*)(WB) + h * 33; \
        _Pragma("unroll") \
        for (int nn = 0; nn < 4; nn++) { \
            const float4* av = (const float4*)((ACT) + (ng + nn) * 128); \
            float a = 0.0f; \
            _Pragma("unroll 8") \
            for (int f4 = 0; f4 < 32; f4++) { \
                float4 x = av[f4]; \
                float4 wv = _wt[f4]; \
                a += x.x * wv.x + x.y * wv.y + x.z * wv.z + x.w * wv.w; \
            } \
            (OUTARR)[nn] = a; \
        } \
    } while (0)

    float acc[4];
    float rr[4], ii[4];

    MBAR_WAIT(mb0, 0);
    GEMV4(aggS, (sm + ND_WB0), acc);
    #pragma unroll
    for (int nn = 0; nn < 4; nn++) {
        int n = ng + nn;
        float a = acc[nn] + biaS[h];
        #pragma unroll
        for (int d = 0; d < 4; d++) a += insS[n*4+d] * WinS[d*128 + h];
        t1[n*128 + h] = fsig_(a);
    }
    __syncthreads();
    if (tid == 0) { MBAR_EXPECT_TX(mb0, TILEF_B); BULK_CP(smb + ND_WB0, (const char*)(g_WnT + (size_t)2 * 128 * SPW), TILEF_B, mb0); }

    MBAR_WAIT(mb1, 0);
    GEMV4(aggS, (sm + ND_WB1), acc);
    #pragma unroll
    for (int nn = 0; nn < 4; nn++) {
        int n = ng + nn;
        float a = acc[nn] + biaS[128 + h];
        #pragma unroll
        for (int d = 0; d < 4; d++) a += insS[n*4+d] * WinS[512 + d*128 + h];
        ii[nn] = fsig_(a);
        rr[nn] = t1[n*128 + h];
    }
    __syncthreads();
    if (tid == 0) { MBAR_EXPECT_TX(mb1, TILEF_B); BULK_CP(smb + ND_WB1, (const char*)(g_WnT + (size_t)3 * 128 * SPW), TILEF_B, mb1); }

    MBAR_WAIT(mb0, 1);
    GEMV4(aggS, (sm + ND_WB0), acc);
    #pragma unroll
    for (int nn = 0; nn < 4; nn++) {
        int n = ng + nn;
        float a = biaS[256 + h];
        #pragma unroll
        for (int d = 0; d < 4; d++) a += insS[n*4+d] * WinS[1024 + d*128 + h];
        float nv = ftanh_(a + rr[nn] * acc[nn]);
        float hn = (1.0f - ii[nn]) * nv + ii[nn] * hidS[n*128 + h];
        hidS[n*128 + h] = hn;
        g_hidden[((size_t)(b * NN + n0 + n)) * HH + h] = hn;
    }
    __syncthreads();
    if (tid == 0) { MBAR_EXPECT_TX(mb0, TILEF_B); BULK_CP(smb + ND_WB0, (const char*)(g_WnT + (size_t)4 * 128 * SPW), TILEF_B, mb0); }

    MBAR_WAIT(mb1, 1);
    GEMV4(hidS, (sm + ND_WB1), acc);
    #pragma unroll
    for (int nn = 0; nn < 4; nn++)
        t1[(ng+nn)*128 + h] = fmaxf(acc[nn] + biaS[384 + h], 0.0f);
    __syncthreads();

    MBAR_WAIT(mb0, 0);
    GEMV4(t1, (sm + ND_WB0), acc);
    #pragma unroll
    for (int nn = 0; nn < 4; nn++)
        t2[(ng+nn)*128 + h] = fmaxf(acc[nn] + biaS[512 + h], 0.0f);
    __syncthreads();

    if (tid < 64) {
        int n = tid >> 2, d = tid & 3;
        float a = bo3S[d];
        const float* vv = t2 + n*128;
        #pragma unroll 8
        for (int hh = 0; hh < 128; hh++) a += vv[hh] * Wo3S[hh*4 + d];
        float pred = insS[tid] + a;
        g_pred[(b * NN + n0 + n) * DD + d] = pred;
        if (step >= TT)
            out[(((size_t)(b * NN + n0 + n)) * DD + d) * LL + (step - TT)] = pred;
    }
    #undef GEMV4
}

// ---------------- launch ----------------
extern "C" void kernel_launch(void* const* d_in, const int* in_sizes, int n_in,
                              void* d_out, int out_size) {
    const float* data  = (const float*)d_in[0];
    const float* rel   = (const float*)d_in[1];
    const float* W1    = (const float*)d_in[2];
    const float* b1    = (const float*)d_in[3];
    const float* W2    = (const float*)d_in[4];
    const float* b2    = (const float*)d_in[5];
    const float* Wr_h  = (const float*)d_in[6];
    const float* Wi_h  = (const float*)d_in[7];
    const float* Wh_h  = (const float*)d_in[8];
    const float* Wr_in = (const float*)d_in[9];
    const float* br_in = (const float*)d_in[10];
    const float* Wi_in = (const float*)d_in[11];
    const float* bi_in = (const float*)d_in[12];
    const float* Wn_in = (const float*)d_in[13];
    const float* bn_in = (const float*)d_in[14];
    const float* Wo1   = (const float*)d_in[15];
    const float* bo1   = (const float*)d_in[16];
    const float* Wo2   = (const float*)d_in[17];
    const float* bo2   = (const float*)d_in[18];
    const float* Wo3   = (const float*)d_in[19];
    const float* bo3   = (const float*)d_in[20];
    const int* recv_idx = (const int*)d_in[21];
    const int* send_idx = (const int*)d_in[22];
    float* out = (float*)d_out;

    cudaFuncSetAttribute(uv_kernel,   cudaFuncAttributeMaxDynamicSharedMemorySize, UV_SMEM);
    cudaFuncSetAttribute(msg_kernel,  cudaFuncAttributeMaxDynamicSharedMemorySize, MSG_SMEM);
    cudaFuncSetAttribute(node_kernel, cudaFuncAttributeMaxDynamicSharedMemorySize, NODE_SMEM);

    init_kernel<<<512, 256>>>();
    prep_kernel<<<17, 256>>>(W1, W2, Wr_h, Wi_h, Wh_h, Wo1, Wo2);
    for (int s = 0; s < TT + LL; s++) {
        uv_kernel<<<dim3(16, 8), 512, UV_SMEM>>>();
        msg_kernel<<<dim3(32, BB, KK), 512, MSG_SMEM>>>(b1, b2, rel, recv_idx, send_idx);
        node_kernel<<<dim3(4, BB), 512, NODE_SMEM>>>(data, s,
            Wr_in, br_in, Wi_in, bi_in, Wn_in, bn_in,
            bo1, bo2, Wo3, bo3, out);
    }
}

// round 16
// speedup vs baseline: 1.2438x; 1.2438x over previous
#include <cuda_runtime.h>
#include <cuda_bf16.h>
#include <stdint.h>
#include <math.h>

#define BB 16
#define NN 64
#define DD 4
#define TT 40
#define LL 10
#define HH 128
#define KK 4
#define EE (NN*(NN-1))

// fp32 tile: 128 x 132 words
#define SPW  132
#define TILEF_B (128*SPW*4)   // 67584
#define UVA_B  (64*SPW*4)     // 33792 (A: 64 rows)
// bf16 tile (msg): 128 x 136 halves (272 B/row)
#define SP   136
#define SPB  272
#define TILEH_B (128*SPB)     // 34816

// ---------------- persistent device state ----------------
__device__ float g_hidden[BB*NN*HH];
__device__ float g_pred[BB*NN*DD];
__device__ __align__(16) __nv_bfloat16 g_uv[BB*8*NN*HH];  // [B][ks][N][H] bf16
__device__ float g_aggk[KK*BB*NN*HH];                     // per-k partial aggregates
__device__ __align__(16) float g_W1T[8*128*SPW];          // fp32 [ks][128][132]
__device__ __align__(16) __nv_bfloat16 g_W2T[4*128*SP];   // bf16 [k][128][136]
__device__ __align__(16) float g_WnT[5*128*SPW];          // node weights^T padded [m][h][132]

// ---------------- PTX helpers ----------------
__device__ __forceinline__ uint32_t smem_u32(const void* p) {
    uint32_t a;
    asm("{ .reg .u64 t; cvta.to.shared.u64 t, %1; cvt.u32.u64 %0, t; }" : "=r"(a) : "l"(p));
    return a;
}
#define MBAR_INIT(mb, c)  asm volatile("mbarrier.init.shared.b64 [%0], %1;" :: "r"(mb), "r"(c) : "memory")
#define MBAR_EXPECT_TX(mb, n) asm volatile("mbarrier.arrive.expect_tx.shared.b64 _, [%0], %1;" :: "r"(mb), "r"(n) : "memory")
#define FENCE_ASYNC()     asm volatile("fence.proxy.async.shared::cta;" ::: "memory")
#define BULK_CP(dst, src, bytes, mb) \
    asm volatile("cp.async.bulk.shared::cta.global.mbarrier::complete_tx::bytes [%0], [%1], %2, [%3];" \
        :: "r"(dst), "l"(src), "r"(bytes), "r"(mb) : "memory")

#define MBAR_WAIT(mb, ph) do { \
    uint32_t _m = (mb); uint32_t _p = (ph); uint32_t _d; \
    asm volatile("{\n\t.reg .pred p;\n\tmbarrier.try_wait.parity.acquire.cta.shared::cta.b64 p, [%1], %2;\n\tselp.b32 %0, 1, 0, p;\n\t}" \
        : "=r"(_d) : "r"(_m), "r"(_p) : "memory"); \
    if (!_d) { \
        asm volatile("{\n\t.reg .pred P1;\n\tWL_%=:\n\tmbarrier.try_wait.parity.acquire.cta.shared::cta.b64 P1, [%0], %1, 0x989680;\n\t@P1 bra.uni WD_%=;\n\tbra.uni WL_%=;\n\tWD_%=:\n\t}" \
            :: "r"(_m), "r"(_p) : "memory"); \
    } \
} while (0)

// tf32 mma m16n8k8
__device__ __forceinline__ void mma_tf32(float d[4], uint32_t a0, uint32_t a1, uint32_t a2, uint32_t a3,
                                         uint32_t b0, uint32_t b1) {
    asm volatile("mma.sync.aligned.m16n8k8.row.col.f32.tf32.tf32.f32 "
        "{%0,%1,%2,%3}, {%4,%5,%6,%7}, {%8,%9}, {%0,%1,%2,%3};"
        : "+f"(d[0]), "+f"(d[1]), "+f"(d[2]), "+f"(d[3])
        : "r"(a0), "r"(a1), "r"(a2), "r"(a3), "r"(b0), "r"(b1));
}
// bf16 mma m16n8k16
__device__ __forceinline__ void mma_bf16(float d[4], uint32_t a0, uint32_t a1, uint32_t a2, uint32_t a3,
                                         uint32_t b0, uint32_t b1) {
    asm volatile("mma.sync.aligned.m16n8k16.row.col.f32.bf16.bf16.f32 "
        "{%0,%1,%2,%3}, {%4,%5,%6,%7}, {%8,%9}, {%0,%1,%2,%3};"
        : "+f"(d[0]), "+f"(d[1]), "+f"(d[2]), "+f"(d[3])
        : "r"(a0), "r"(a1), "r"(a2), "r"(a3), "r"(b0), "r"(b1));
}
__device__ __forceinline__ void ldsm_x4(uint32_t& r0, uint32_t& r1, uint32_t& r2, uint32_t& r3, uint32_t addr) {
    asm volatile("ldmatrix.sync.aligned.m8n8.x4.shared.b16 {%0,%1,%2,%3}, [%4];"
        : "=r"(r0), "=r"(r1), "=r"(r2), "=r"(r3) : "r"(addr));
}

// tf32 GEMM (uv): 16 warps, warp tile 16m x 32n (M=64, N=128 per block)
__device__ __forceinline__ void gemm_tf32_16(const float* __restrict__ A, const float* __restrict__ B,
                                             float acc[4][4], int mblk, int nblk, int lane) {
    int gid = lane >> 2, tig = lane & 3;
    const float* ap0 = A + (mblk * 16 + gid) * SPW + tig;
    const float* bp0 = B + (nblk * 32 + gid) * SPW + tig;
    #pragma unroll
    for (int ks = 0; ks < 16; ks++) {
        int k0 = ks * 8;
        uint32_t a0 = __float_as_uint(ap0[k0]);
        uint32_t a1 = __float_as_uint(ap0[8 * SPW + k0]);
        uint32_t a2 = __float_as_uint(ap0[k0 + 4]);
        uint32_t a3 = __float_as_uint(ap0[8 * SPW + k0 + 4]);
        #pragma unroll
        for (int nf = 0; nf < 4; nf++) {
            const float* bp = bp0 + nf * 8 * SPW + k0;
            uint32_t b0 = __float_as_uint(bp[0]);
            uint32_t b1 = __float_as_uint(bp[4]);
            mma_tf32(acc[nf], a0, a1, a2, a3, b0, b1);
        }
    }
}

// bf16 GEMM via ldmatrix: warp tile 32m x 32n
__device__ __forceinline__ void gemm_bf16_ldsm(uint32_t smA, uint32_t smB,
                                               float acc[2][4][4], int mblk, int nblk, int lane) {
    uint32_t aB0 = smA + (uint32_t)(mblk * 32 + (lane & 15)) * SPB + (uint32_t)(lane >> 4) * 16;
    uint32_t aB1 = aB0 + 16 * SPB;
    uint32_t bB0 = smB + (uint32_t)(nblk * 32 + ((lane >> 4) << 3) + (lane & 7)) * SPB
                 + (uint32_t)((lane >> 3) & 1) * 16;
    uint32_t bB1 = bB0 + 16 * SPB;
    #pragma unroll
    for (int ks = 0; ks < 8; ks++) {
        uint32_t kb = (uint32_t)ks * 32;
        uint32_t a0[4], a1[4], b0[4], b1[4];
        ldsm_x4(a0[0], a0[1], a0[2], a0[3], aB0 + kb);
        ldsm_x4(a1[0], a1[1], a1[2], a1[3], aB1 + kb);
        ldsm_x4(b0[0], b0[1], b0[2], b0[3], bB0 + kb);
        ldsm_x4(b1[0], b1[1], b1[2], b1[3], bB1 + kb);
        mma_bf16(acc[0][0], a0[0], a0[1], a0[2], a0[3], b0[0], b0[1]);
        mma_bf16(acc[1][0], a1[0], a1[1], a1[2], a1[3], b0[0], b0[1]);
        mma_bf16(acc[0][1], a0[0], a0[1], a0[2], a0[3], b0[2], b0[3]);
        mma_bf16(acc[1][1], a1[0], a1[1], a1[2], a1[3], b0[2], b0[3]);
        mma_bf16(acc[0][2], a0[0], a0[1], a0[2], a0[3], b1[0], b1[1]);
        mma_bf16(acc[1][2], a1[0], a1[1], a1[2], a1[3], b1[0], b1[1]);
        mma_bf16(acc[0][3], a0[0], a0[1], a0[2], a0[3], b1[2], b1[3]);
        mma_bf16(acc[1][3], a1[0], a1[1], a1[2], a1[3], b1[2], b1[3]);
    }
}

// ---------------- fast math ----------------
__device__ __forceinline__ float fex2_(float x) { float r; asm("ex2.approx.f32 %0, %1;" : "=f"(r) : "f"(x)); return r; }
__device__ __forceinline__ float frcp_(float x) { float r; asm("rcp.approx.f32 %0, %1;" : "=f"(r) : "f"(x)); return r; }
__device__ __forceinline__ float ftanh_(float x) { return fmaf(-2.0f, frcp_(fex2_(x * 2.885390081777927f) + 1.0f), 1.0f); }
__device__ __forceinline__ float fsig_(float x)  { return frcp_(1.0f + fex2_(-1.4426950408889634f * x)); }
__device__ __forceinline__ float ftanha_(float x){ float r; asm("tanh.approx.f32 %0, %1;" : "=f"(r) : "f"(x)); return r; }

// ---------------- init ----------------
__global__ void init_kernel() {
    int i = blockIdx.x * blockDim.x + threadIdx.x;
    if (i < BB*NN*HH) g_hidden[i] = 0.0f;
    if (i < BB*NN*DD) g_pred[i]   = 0.0f;
}

// ---------------- prep ----------------
__global__ __launch_bounds__(256)
void prep_kernel(const float* __restrict__ W1, const float* __restrict__ W2,
                 const float* __restrict__ Wr_h, const float* __restrict__ Wi_h,
                 const float* __restrict__ Wh_h, const float* __restrict__ Wo1,
                 const float* __restrict__ Wo2) {
    int s = blockIdx.x;
    if (s < 8) {
        const float* src = W1 + s * 16384;
        float* dst = g_W1T + s * 128 * SPW;
        for (int t = threadIdx.x; t < 16384; t += 256) {
            int n = t >> 7, f = t & 127;
            dst[n * SPW + f] = src[f * 128 + n];
        }
    } else if (s < 12) {
        const float* src = W2 + (s - 8) * 16384;
        __nv_bfloat16* dst = g_W2T + (s - 8) * 128 * SP;
        for (int t = threadIdx.x; t < 16384; t += 256) {
            int n = t >> 7, f = t & 127;
            dst[n * SP + f] = __float2bfloat16_rn(src[f * 128 + n]);
        }
    } else {
        const float* src;
        switch (s - 12) {
            case 0: src = Wr_h; break;
            case 1: src = Wi_h; break;
            case 2: src = Wh_h; break;
            case 3: src = Wo1;  break;
            default: src = Wo2; break;
        }
        float* dst = g_WnT + (s - 12) * 128 * SPW;
        for (int t = threadIdx.x; t < 16384; t += 256) {
            int h = t >> 7, f = t & 127;
            dst[h * SPW + f] = src[f * 128 + h];
        }
    }
}

// ---------------- UV: tf32 GEMM, M-split (one batch per block), bf16 output ----------------
#define UV_A  0
#define UV_B  UVA_B
#define UV_MB (UVA_B + TILEF_B)
#define UV_SMEM (UV_MB + 32)

__global__ __launch_bounds__(512)
void uv_kernel() {
    extern __shared__ char sm[];
    uint32_t smb = smem_u32(sm);
    int tid = threadIdx.x;
    int ks = blockIdx.x, b = blockIdx.y;   // 8 x 16 = 128 blocks
    uint32_t mbt = smb + UV_MB;
    float* A = (float*)(sm + UV_A);
    const float* Bt = (const float*)(sm + UV_B);

    if (tid == 0) {
        MBAR_INIT(mbt, 1);
        FENCE_ASYNC();
        MBAR_EXPECT_TX(mbt, TILEF_B);
        BULK_CP(smb + UV_B, (const char*)(g_W1T + (size_t)ks * 128 * SPW), TILEF_B, mbt);
    }
    // A: 64 rows (this batch's nodes)
    for (int idx = tid; idx < 64 * 32; idx += 512) {
        int row = idx >> 5, f4 = (idx & 31) * 4;
        float4 v = *(const float4*)(g_hidden + ((size_t)(b * NN + row)) * HH + f4);
        *(float4*)&A[row * SPW + f4] = v;
    }
    __syncthreads();
    MBAR_WAIT(mbt, 0);

    int w = tid >> 5, lane = tid & 31;
    int mblk = w & 3, nblk = w >> 2;   // 4 m-blocks x 4 n-blocks, tile 16m x 32n
    int gid = lane >> 2, tig = lane & 3;

    float acc[4][4];
    #pragma unroll
    for (int nf = 0; nf < 4; nf++)
        #pragma unroll
        for (int j = 0; j < 4; j++) acc[nf][j] = 0.0f;

    gemm_tf32_16(A, Bt, acc, mblk, nblk, lane);
    __syncthreads();   // done reading A; reuse as fp32 staging (64 x 128)

    {
        int r0 = mblk * 16 + gid;
        #pragma unroll
        for (int nf = 0; nf < 4; nf++) {
            int c = nblk * 32 + nf * 8 + tig * 2;
            *(float2*)&A[r0 * SPW + c]       = make_float2(acc[nf][0], acc[nf][1]);
            *(float2*)&A[(r0 + 8) * SPW + c] = make_float2(acc[nf][2], acc[nf][3]);
        }
    }
    __syncthreads();
    for (int idx = tid; idx < 64 * 16; idx += 512) {
        int row = idx >> 4, c8 = (idx & 15) * 8;
        float4 v0 = *(const float4*)&A[row * SPW + c8];
        float4 v1 = *(const float4*)&A[row * SPW + c8 + 4];
        __nv_bfloat162 p0 = __floats2bfloat162_rn(v0.x, v0.y);
        __nv_bfloat162 p1 = __floats2bfloat162_rn(v0.z, v0.w);
        __nv_bfloat162 p2 = __floats2bfloat162_rn(v1.x, v1.y);
        __nv_bfloat162 p3 = __floats2bfloat162_rn(v1.z, v1.w);
        __nv_bfloat162* dst = (__nv_bfloat162*)(g_uv + ((size_t)(b * 8 + ks) * 64 + row) * 128 + c8);
        dst[0] = p0; dst[1] = p1; dst[2] = p2; dst[3] = p3;
    }
}

// ---------------- MSG kernel: one block per (pair, batch, k); 2 CTAs/SM ----------------
#define MS_A    0
#define MS_B    34816
#define MS_U    69632
#define MS_VS   86016
#define MS_SCR  87040
#define MS_REL  89088
#define MS_SEND 89600
#define MS_B2   90112
#define MS_MB   90624
#define MSG_SMEM 90656

__global__ __launch_bounds__(512, 2)
void msg_kernel(const float* __restrict__ b1, const float* __restrict__ b2,
                const float* __restrict__ rel,
                const int* __restrict__ recv_idx, const int* __restrict__ send_idx) {
    extern __shared__ char sm[];
    uint32_t smb = smem_u32(sm);
    int tid = threadIdx.x;
    int p = blockIdx.x, b = blockIdx.y, k = blockIdx.z;

    float* RelS  = (float*)(sm + MS_REL);
    int*   SendS = (int*)(sm + MS_SEND);
    float* b2S   = (float*)(sm + MS_B2);
    float* vS    = (float*)(sm + MS_VS);
    float* scr   = (float*)(sm + MS_SCR);
    uint32_t bbar = smb + MS_MB, ubar = smb + MS_MB + 8;

    if (tid == 0) {
        MBAR_INIT(bbar, 1);
        MBAR_INIT(ubar, 1);
        FENCE_ASYNC();
        MBAR_EXPECT_TX(bbar, TILEH_B);
        BULK_CP(smb + MS_B, (const char*)(g_W2T + (size_t)k * 128 * SP), TILEH_B, bbar);
        MBAR_EXPECT_TX(ubar, 16384);
        BULK_CP(smb + MS_U, (const char*)(g_uv + (size_t)(b * 8 + 2 * k) * 8192), 16384, ubar);
    }
    int r0n = recv_idx[p * 126];
    int r1n = recv_idx[p * 126 + 63];
    if (tid < 128) {
        int row = tid;
        float rw = 0.0f;
        int sn = 0;
        if (row != 63 && row != 127) {
            int e = (row < 64) ? (p * 126 + row) : (p * 126 + row - 1);
            sn = send_idx[e];
            rw = rel[((size_t)(b * EE + e)) * KK + k];
        }
        SendS[row] = sn;
        RelS[row] = rw;
        b2S[row] = b2[k * 128 + row];
    } else if (tid < 384) {
        int f = tid & 127, rh = (tid >> 7) & 1;
        int rv = rh ? r1n : r0n;
        const __nv_bfloat16* v = g_uv + ((size_t)(b * 8 + 2 * k + 1)) * 8192 + rv * 128;
        vS[rh * 128 + f] = __bfloat162float(v[f]) + b1[k * 128 + f];
    }
    __syncthreads();   // mbarrier init + vS/metadata visible

    // build A = bf16(tanh(u[send] + vS)); rows 63/127 zero.
    MBAR_WAIT(ubar, 0);
    {
        const __nv_bfloat16* U = (const __nv_bfloat16*)(sm + MS_U);
        int f4 = (tid & 31) * 4;
        int rowbase = tid >> 5;
        float4 vv0 = *(const float4*)&vS[f4];
        float4 vv1 = *(const float4*)&vS[128 + f4];
        char* Abase = sm + MS_A + f4 * 2;
        #pragma unroll
        for (int it = 0; it < 8; it++) {
            int row = rowbase + 16 * it;
            uint32_t o01 = 0, o23 = 0;
            if (row != 63 && row != 127) {
                int sn = SendS[row];
                float4 vv = (row < 64) ? vv0 : vv1;
                uint2 q = *(const uint2*)(U + sn * 128 + f4);
                float2 f0 = __bfloat1622float2(*(__nv_bfloat162*)&q.x);
                float2 f1 = __bfloat1622float2(*(__nv_bfloat162*)&q.y);
                __nv_bfloat162 p0 = __floats2bfloat162_rn(ftanha_(f0.x + vv.x), ftanha_(f0.y + vv.y));
                __nv_bfloat162 p1 = __floats2bfloat162_rn(ftanha_(f1.x + vv.z), ftanha_(f1.y + vv.w));
                o01 = *(uint32_t*)&p0; o23 = *(uint32_t*)&p1;
            }
            *(uint2*)(Abase + row * SPB) = make_uint2(o01, o23);
        }
    }
    __syncthreads();

    MBAR_WAIT(bbar, 0);
    int w = tid >> 5, lane = tid & 31;
    int mblk = w & 3, nblk = w >> 2;
    int gid = lane >> 2, tig = lane & 3;

    float acc[2][4][4];
    #pragma unroll
    for (int mf = 0; mf < 2; mf++)
        #pragma unroll
        for (int nf = 0; nf < 4; nf++)
            #pragma unroll
            for (int j = 0; j < 4; j++) acc[mf][nf][j] = 0.0f;

    gemm_bf16_ldsm(smb + MS_A, smb + MS_B, acc, mblk, nblk, lane);

    // fused epilogue + row-sum
    float sum[4][2];
    #pragma unroll
    for (int nf = 0; nf < 4; nf++) { sum[nf][0] = 0.0f; sum[nf][1] = 0.0f; }
    {
        int r0 = mblk * 32 + gid;
        float rw0 = RelS[r0];
        float rw1 = RelS[r0 + 8];
        float rw2 = RelS[r0 + 16];
        float rw3 = RelS[r0 + 24];
        #pragma unroll
        for (int nf = 0; nf < 4; nf++) {
            int c = nblk * 32 + nf * 8 + tig * 2;
            float bb0 = b2S[c], bb1 = b2S[c + 1];
            sum[nf][0] += rw0 * ftanha_(acc[0][nf][0] + bb0)
                        + rw1 * ftanha_(acc[0][nf][2] + bb0)
                        + rw2 * ftanha_(acc[1][nf][0] + bb0)
                        + rw3 * ftanha_(acc[1][nf][2] + bb0);
            sum[nf][1] += rw0 * ftanha_(acc[0][nf][1] + bb1)
                        + rw1 * ftanha_(acc[0][nf][3] + bb1)
                        + rw2 * ftanha_(acc[1][nf][1] + bb1)
                        + rw3 * ftanha_(acc[1][nf][3] + bb1);
        }
    }
    #pragma unroll
    for (int off = 16; off >= 4; off >>= 1)
        #pragma unroll
        for (int nf = 0; nf < 4; nf++) {
            sum[nf][0] += __shfl_down_sync(0xffffffffu, sum[nf][0], off);
            sum[nf][1] += __shfl_down_sync(0xffffffffu, sum[nf][1], off);
        }
    if (gid == 0) {
        #pragma unroll
        for (int nf = 0; nf < 4; nf++) {
            int c = nblk * 32 + nf * 8 + tig * 2;
            *(float2*)&scr[mblk * 128 + c] = make_float2(sum[nf][0], sum[nf][1]);
        }
    }
    __syncthreads();
    if (tid < 256) {
        int h = tid & 127, rh = tid >> 7;
        float a = scr[(rh * 2) * 128 + h] + scr[(rh * 2 + 1) * 128 + h];
        int rv = rh ? r1n : r0n;
        g_aggk[(((size_t)k * BB + b) * NN + rv) * HH + h] = a;
    }
}

// ---------------- NODE kernel (transposed padded weights, 256 thr, 128 blocks) ----------------
#define ND_WB0 0
#define ND_WB1 67584
#define ND_AGG 135168
#define ND_HID 139264
#define ND_T1  143360
#define ND_T2  147456
#define ND_INS 151552
#define ND_WIN 151808
#define ND_BIA 157952
#define ND_WO3 160512
#define ND_BO3 162560
#define ND_MB  162576
#define NODE_SMEM 162640

__global__ __launch_bounds__(256)
void node_kernel(const float* __restrict__ data, int step,
                 const float* __restrict__ Wr_in, const float* __restrict__ br_in,
                 const float* __restrict__ Wi_in, const float* __restrict__ bi_in,
                 const float* __restrict__ Wn_in, const float* __restrict__ bn_in,
                 const float* __restrict__ bo1, const float* __restrict__ bo2,
                 const float* __restrict__ Wo3, const float* __restrict__ bo3,
                 float* __restrict__ out) {
    extern __shared__ char sm[];
    uint32_t smb = smem_u32(sm);
    int q = blockIdx.x, b = blockIdx.y;
    int n0 = q * 8;
    int tid = threadIdx.x;

    float* aggS = (float*)(sm + ND_AGG);
    float* hidS = (float*)(sm + ND_HID);
    float* t1   = (float*)(sm + ND_T1);
    float* t2   = (float*)(sm + ND_T2);
    float* insS = (float*)(sm + ND_INS);
    float* WinS = (float*)(sm + ND_WIN);
    float* biaS = (float*)(sm + ND_BIA);
    float* Wo3S = (float*)(sm + ND_WO3);
    float* bo3S = (float*)(sm + ND_BO3);
    uint32_t mb0 = smb + ND_MB, mb1 = smb + ND_MB + 8;

    if (tid == 0) {
        MBAR_INIT(mb0, 1);
        MBAR_INIT(mb1, 1);
        FENCE_ASYNC();
        MBAR_EXPECT_TX(mb0, TILEF_B);
        BULK_CP(smb + ND_WB0, (const char*)(g_WnT + 0), TILEF_B, mb0);
        MBAR_EXPECT_TX(mb1, TILEF_B);
        BULK_CP(smb + ND_WB1, (const char*)(g_WnT + (size_t)1 * 128 * SPW), TILEF_B, mb1);
    }
    {
        size_t base = ((size_t)(b * NN + n0)) * HH;
        const float4* a0 = (const float4*)(g_aggk + base);
        const float4* a1 = (const float4*)(g_aggk + base + (size_t)BB * NN * HH);
        const float4* a2 = (const float4*)(g_aggk + base + (size_t)2 * BB * NN * HH);
        const float4* a3 = (const float4*)(g_aggk + base + (size_t)3 * BB * NN * HH);
        float4 s0 = a0[tid], s1 = a1[tid], s2 = a2[tid], s3 = a3[tid];
        float4 s;
        s.x = (s0.x + s1.x + s2.x + s3.x) * (1.0f / 16.0f);
        s.y = (s0.y + s1.y + s2.y + s3.y) * (1.0f / 16.0f);
        s.z = (s0.z + s1.z + s2.z + s3.z) * (1.0f / 16.0f);
        s.w = (s0.w + s1.w + s2.w + s3.w) * (1.0f / 16.0f);
        ((float4*)aggS)[tid] = s;
        const float* hg = g_hidden + base;
        ((float4*)hidS)[tid] = ((const float4*)hg)[tid];
    }
    if (tid < 32) {
        int n = tid >> 2, d = tid & 3;
        float v;
        if (step < TT) v = data[(((size_t)(b * NN + n0 + n)) * DD + d) * TT + step];
        else           v = g_pred[(b * NN + n0 + n) * DD + d];
        insS[tid] = v;
    }
    for (int i = tid; i < 512; i += 256) {
        WinS[i]        = Wr_in[i];
        WinS[512 + i]  = Wi_in[i];
        WinS[1024 + i] = Wn_in[i];
        Wo3S[i]        = Wo3[i];
    }
    if (tid < 128) {
        biaS[tid]       = br_in[tid];
        biaS[128 + tid] = bi_in[tid];
        biaS[256 + tid] = bn_in[tid];
        biaS[384 + tid] = bo1[tid];
        biaS[512 + tid] = bo2[tid];
    }
    if (tid < 4) bo3S[tid] = bo3[tid];
    __syncthreads();

    int h = tid & 127, ng = (tid >> 7) * 4;

    #define GEMV4(ACT, WB, OUTARR) do { \
        const float4* _wt = (const float4*)(WB) + h * 33; \
        _Pragma("unroll") \
        for (int nn = 0; nn < 4; nn++) { \
            const float4* av = (const float4*)((ACT) + (ng + nn) * 128); \
            float a = 0.0f; \
            _Pragma("unroll 8") \
            for (int f4 = 0; f4 < 32; f4++) { \
                float4 x = av[f4]; \
                float4 wv = _wt[f4]; \
                a += x.x * wv.x + x.y * wv.y + x.z * wv.z + x.w * wv.w; \
            } \
            (OUTARR)[nn] = a; \
        } \
    } while (0)

    float acc[4];
    float rr[4], ii[4];

    MBAR_WAIT(mb0, 0);
    GEMV4(aggS, (sm + ND_WB0), acc);
    #pragma unroll
    for (int nn = 0; nn < 4; nn++) {
        int n = ng + nn;
        float a = acc[nn] + biaS[h];
        #pragma unroll
        for (int d = 0; d < 4; d++) a += insS[n*4+d] * WinS[d*128 + h];
        t1[n*128 + h] = fsig_(a);
    }
    __syncthreads();
    if (tid == 0) { MBAR_EXPECT_TX(mb0, TILEF_B); BULK_CP(smb + ND_WB0, (const char*)(g_WnT + (size_t)2 * 128 * SPW), TILEF_B, mb0); }

    MBAR_WAIT(mb1, 0);
    GEMV4(aggS, (sm + ND_WB1), acc);
    #pragma unroll
    for (int nn = 0; nn < 4; nn++) {
        int n = ng + nn;
        float a = acc[nn] + biaS[128 + h];
        #pragma unroll
        for (int d = 0; d < 4; d++) a += insS[n*4+d] * WinS[512 + d*128 + h];
        ii[nn] = fsig_(a);
        rr[nn] = t1[n*128 + h];
    }
    __syncthreads();
    if (tid == 0) { MBAR_EXPECT_TX(mb1, TILEF_B); BULK_CP(smb + ND_WB1, (const char*)(g_WnT + (size_t)3 * 128 * SPW), TILEF_B, mb1); }

    MBAR_WAIT(mb0, 1);
    GEMV4(aggS, (sm + ND_WB0), acc);
    #pragma unroll
    for (int nn = 0; nn < 4; nn++) {
        int n = ng + nn;
        float a = biaS[256 + h];
        #pragma unroll
        for (int d = 0; d < 4; d++) a += insS[n*4+d] * WinS[1024 + d*128 + h];
        float nv = ftanh_(a + rr[nn] * acc[nn]);
        float hn = (1.0f - ii[nn]) * nv + ii[nn] * hidS[n*128 + h];
        hidS[n*128 + h] = hn;
        g_hidden[((size_t)(b * NN + n0 + n)) * HH + h] = hn;
    }
    __syncthreads();
    if (tid == 0) { MBAR_EXPECT_TX(mb0, TILEF_B); BULK_CP(smb + ND_WB0, (const char*)(g_WnT + (size_t)4 * 128 * SPW), TILEF_B, mb0); }

    MBAR_WAIT(mb1, 1);
    GEMV4(hidS, (sm + ND_WB1), acc);
    #pragma unroll
    for (int nn = 0; nn < 4; nn++)
        t1[(ng+nn)*128 + h] = fmaxf(acc[nn] + biaS[384 + h], 0.0f);
    __syncthreads();

    MBAR_WAIT(mb0, 0);
    GEMV4(t1, (sm + ND_WB0), acc);
    #pragma unroll
    for (int nn = 0; nn < 4; nn++)
        t2[(ng+nn)*128 + h] = fmaxf(acc[nn] + biaS[512 + h], 0.0f);
    __syncthreads();

    if (tid < 32) {
        int n = tid >> 2, d = tid & 3;
        float a = bo3S[d];
        const float* vv = t2 + n*128;
        #pragma unroll 8
        for (int hh = 0; hh < 128; hh++) a += vv[hh] * Wo3S[hh*4 + d];
        float pred = insS[tid] + a;
        g_pred[(b * NN + n0 + n) * DD + d] = pred;
        if (step >= TT)
            out[(((size_t)(b * NN + n0 + n)) * DD + d) * LL + (step - TT)] = pred;
    }
    #undef GEMV4
}

// ---------------- launch ----------------
extern "C" void kernel_launch(void* const* d_in, const int* in_sizes, int n_in,
                              void* d_out, int out_size) {
    const float* data  = (const float*)d_in[0];
    const float* rel   = (const float*)d_in[1];
    const float* W1    = (const float*)d_in[2];
    const float* b1    = (const float*)d_in[3];
    const float* W2    = (const float*)d_in[4];
    const float* b2    = (const float*)d_in[5];
    const float* Wr_h  = (const float*)d_in[6];
    const float* Wi_h  = (const float*)d_in[7];
    const float* Wh_h  = (const float*)d_in[8];
    const float* Wr_in = (const float*)d_in[9];
    const float* br_in = (const float*)d_in[10];
    const float* Wi_in = (const float*)d_in[11];
    const float* bi_in = (const float*)d_in[12];
    const float* Wn_in = (const float*)d_in[13];
    const float* bn_in = (const float*)d_in[14];
    const float* Wo1   = (const float*)d_in[15];
    const float* bo1   = (const float*)d_in[16];
    const float* Wo2   = (const float*)d_in[17];
    const float* bo2   = (const float*)d_in[18];
    const float* Wo3   = (const float*)d_in[19];
    const float* bo3   = (const float*)d_in[20];
    const int* recv_idx = (const int*)d_in[21];
    const int* send_idx = (const int*)d_in[22];
    float* out = (float*)d_out;

    cudaFuncSetAttribute(uv_kernel,   cudaFuncAttributeMaxDynamicSharedMemorySize, UV_SMEM);
    cudaFuncSetAttribute(msg_kernel,  cudaFuncAttributeMaxDynamicSharedMemorySize, MSG_SMEM);
    cudaFuncSetAttribute(node_kernel, cudaFuncAttributeMaxDynamicSharedMemorySize, NODE_SMEM);

    init_kernel<<<512, 256>>>();
    prep_kernel<<<17, 256>>>(W1, W2, Wr_h, Wi_h, Wh_h, Wo1, Wo2);
    for (int s = 0; s < TT + LL; s++) {
        uv_kernel<<<dim3(8, 16), 512, UV_SMEM>>>();
        msg_kernel<<<dim3(32, BB, KK), 512, MSG_SMEM>>>(b1, b2, rel, recv_idx, send_idx);
        node_kernel<<<dim3(8, BB), 256, NODE_SMEM>>>(data, s,
            Wr_in, br_in, Wi_in, bi_in, Wn_in, bn_in,
            bo1, bo2, Wo3, bo3, out);
    }
}

// round 17
// speedup vs baseline: 1.4263x; 1.1468x over previous
#include <cuda_runtime.h>
#include <cuda_bf16.h>
#include <stdint.h>
#include <math.h>

#define BB 16
#define NN 64
#define DD 4
#define TT 40
#define LL 10
#define HH 128
#define KK 4
#define EE (NN*(NN-1))

// fp32 tile: 128 x 132 words
#define SPW  132
#define TILEF_B (128*SPW*4)   // 67584
#define UVA_B  (64*SPW*4)     // 33792 (A: 64 rows)
// bf16 tile (msg): 128 x 136 halves (272 B/row)
#define SP   136
#define SPB  272
#define TILEH_B (128*SPB)     // 34816

// ---------------- persistent device state ----------------
__device__ float g_hidden[BB*NN*HH];
__device__ float g_pred[BB*NN*DD];
__device__ __align__(16) __nv_bfloat16 g_uv[BB*8*NN*HH];  // [B][ks][N][H] bf16
__device__ float g_aggk[KK*BB*NN*HH];                     // per-k partial aggregates
__device__ __align__(16) float g_W1T[8*128*SPW];          // fp32 [ks][128][132]
__device__ __align__(16) __nv_bfloat16 g_W2T[4*128*SP];   // bf16 [k][128][136]
__device__ __align__(16) float g_WnT[5*128*SPW];          // node weights^T padded [m][h][132]

// ---------------- PTX helpers ----------------
__device__ __forceinline__ uint32_t smem_u32(const void* p) {
    uint32_t a;
    asm("{ .reg .u64 t; cvta.to.shared.u64 t, %1; cvt.u32.u64 %0, t; }" : "=r"(a) : "l"(p));
    return a;
}
#define MBAR_INIT(mb, c)  asm volatile("mbarrier.init.shared.b64 [%0], %1;" :: "r"(mb), "r"(c) : "memory")
#define MBAR_EXPECT_TX(mb, n) asm volatile("mbarrier.arrive.expect_tx.shared.b64 _, [%0], %1;" :: "r"(mb), "r"(n) : "memory")
#define FENCE_ASYNC()     asm volatile("fence.proxy.async.shared::cta;" ::: "memory")
#define BULK_CP(dst, src, bytes, mb) \
    asm volatile("cp.async.bulk.shared::cta.global.mbarrier::complete_tx::bytes [%0], [%1], %2, [%3];" \
        :: "r"(dst), "l"(src), "r"(bytes), "r"(mb) : "memory")

#define MBAR_WAIT(mb, ph) do { \
    uint32_t _m = (mb); uint32_t _p = (ph); uint32_t _d; \
    asm volatile("{\n\t.reg .pred p;\n\tmbarrier.try_wait.parity.acquire.cta.shared::cta.b64 p, [%1], %2;\n\tselp.b32 %0, 1, 0, p;\n\t}" \
        : "=r"(_d) : "r"(_m), "r"(_p) : "memory"); \
    if (!_d) { \
        asm volatile("{\n\t.reg .pred P1;\n\tWL_%=:\n\tmbarrier.try_wait.parity.acquire.cta.shared::cta.b64 P1, [%0], %1, 0x989680;\n\t@P1 bra.uni WD_%=;\n\tbra.uni WL_%=;\n\tWD_%=:\n\t}" \
            :: "r"(_m), "r"(_p) : "memory"); \
    } \
} while (0)

// tf32 mma m16n8k8
__device__ __forceinline__ void mma_tf32(float d[4], uint32_t a0, uint32_t a1, uint32_t a2, uint32_t a3,
                                         uint32_t b0, uint32_t b1) {
    asm volatile("mma.sync.aligned.m16n8k8.row.col.f32.tf32.tf32.f32 "
        "{%0,%1,%2,%3}, {%4,%5,%6,%7}, {%8,%9}, {%0,%1,%2,%3};"
        : "+f"(d[0]), "+f"(d[1]), "+f"(d[2]), "+f"(d[3])
        : "r"(a0), "r"(a1), "r"(a2), "r"(a3), "r"(b0), "r"(b1));
}
// bf16 mma m16n8k16
__device__ __forceinline__ void mma_bf16(float d[4], uint32_t a0, uint32_t a1, uint32_t a2, uint32_t a3,
                                         uint32_t b0, uint32_t b1) {
    asm volatile("mma.sync.aligned.m16n8k16.row.col.f32.bf16.bf16.f32 "
        "{%0,%1,%2,%3}, {%4,%5,%6,%7}, {%8,%9}, {%0,%1,%2,%3};"
        : "+f"(d[0]), "+f"(d[1]), "+f"(d[2]), "+f"(d[3])
        : "r"(a0), "r"(a1), "r"(a2), "r"(a3), "r"(b0), "r"(b1));
}
__device__ __forceinline__ void ldsm_x4(uint32_t& r0, uint32_t& r1, uint32_t& r2, uint32_t& r3, uint32_t addr) {
    asm volatile("ldmatrix.sync.aligned.m8n8.x4.shared.b16 {%0,%1,%2,%3}, [%4];"
        : "=r"(r0), "=r"(r1), "=r"(r2), "=r"(r3) : "r"(addr));
}

// tf32 GEMM (uv): 16 warps, warp tile 16m x 32n (M=64, N=128 per block)
__device__ __forceinline__ void gemm_tf32_16(const float* __restrict__ A, const float* __restrict__ B,
                                             float acc[4][4], int mblk, int nblk, int lane) {
    int gid = lane >> 2, tig = lane & 3;
    const float* ap0 = A + (mblk * 16 + gid) * SPW + tig;
    const float* bp0 = B + (nblk * 32 + gid) * SPW + tig;
    #pragma unroll
    for (int ks = 0; ks < 16; ks++) {
        int k0 = ks * 8;
        uint32_t a0 = __float_as_uint(ap0[k0]);
        uint32_t a1 = __float_as_uint(ap0[8 * SPW + k0]);
        uint32_t a2 = __float_as_uint(ap0[k0 + 4]);
        uint32_t a3 = __float_as_uint(ap0[8 * SPW + k0 + 4]);
        #pragma unroll
        for (int nf = 0; nf < 4; nf++) {
            const float* bp = bp0 + nf * 8 * SPW + k0;
            uint32_t b0 = __float_as_uint(bp[0]);
            uint32_t b1 = __float_as_uint(bp[4]);
            mma_tf32(acc[nf], a0, a1, a2, a3, b0, b1);
        }
    }
}

// bf16 GEMM via ldmatrix: warp tile 32m x 32n
__device__ __forceinline__ void gemm_bf16_ldsm(uint32_t smA, uint32_t smB,
                                               float acc[2][4][4], int mblk, int nblk, int lane) {
    uint32_t aB0 = smA + (uint32_t)(mblk * 32 + (lane & 15)) * SPB + (uint32_t)(lane >> 4) * 16;
    uint32_t aB1 = aB0 + 16 * SPB;
    uint32_t bB0 = smB + (uint32_t)(nblk * 32 + ((lane >> 4) << 3) + (lane & 7)) * SPB
                 + (uint32_t)((lane >> 3) & 1) * 16;
    uint32_t bB1 = bB0 + 16 * SPB;
    #pragma unroll
    for (int ks = 0; ks < 8; ks++) {
        uint32_t kb = (uint32_t)ks * 32;
        uint32_t a0[4], a1[4], b0[4], b1[4];
        ldsm_x4(a0[0], a0[1], a0[2], a0[3], aB0 + kb);
        ldsm_x4(a1[0], a1[1], a1[2], a1[3], aB1 + kb);
        ldsm_x4(b0[0], b0[1], b0[2], b0[3], bB0 + kb);
        ldsm_x4(b1[0], b1[1], b1[2], b1[3], bB1 + kb);
        mma_bf16(acc[0][0], a0[0], a0[1], a0[2], a0[3], b0[0], b0[1]);
        mma_bf16(acc[1][0], a1[0], a1[1], a1[2], a1[3], b0[0], b0[1]);
        mma_bf16(acc[0][1], a0[0], a0[1], a0[2], a0[3], b0[2], b0[3]);
        mma_bf16(acc[1][1], a1[0], a1[1], a1[2], a1[3], b0[2], b0[3]);
        mma_bf16(acc[0][2], a0[0], a0[1], a0[2], a0[3], b1[0], b1[1]);
        mma_bf16(acc[1][2], a1[0], a1[1], a1[2], a1[3], b1[0], b1[1]);
        mma_bf16(acc[0][3], a0[0], a0[1], a0[2], a0[3], b1[2], b1[3]);
        mma_bf16(acc[1][3], a1[0], a1[1], a1[2], a1[3], b1[2], b1[3]);
    }
}

// ---------------- fast math ----------------
__device__ __forceinline__ float fex2_(float x) { float r; asm("ex2.approx.f32 %0, %1;" : "=f"(r) : "f"(x)); return r; }
__device__ __forceinline__ float frcp_(float x) { float r; asm("rcp.approx.f32 %0, %1;" : "=f"(r) : "f"(x)); return r; }
__device__ __forceinline__ float ftanh_(float x) { return fmaf(-2.0f, frcp_(fex2_(x * 2.885390081777927f) + 1.0f), 1.0f); }
__device__ __forceinline__ float fsig_(float x)  { return frcp_(1.0f + fex2_(-1.4426950408889634f * x)); }
__device__ __forceinline__ float ftanha_(float x){ float r; asm("tanh.approx.f32 %0, %1;" : "=f"(r) : "f"(x)); return r; }

// ---------------- init ----------------
__global__ void init_kernel() {
    int i = blockIdx.x * blockDim.x + threadIdx.x;
    if (i < BB*NN*HH) g_hidden[i] = 0.0f;
    if (i < BB*NN*DD) g_pred[i]   = 0.0f;
}

// ---------------- prep ----------------
__global__ __launch_bounds__(256)
void prep_kernel(const float* __restrict__ W1, const float* __restrict__ W2,
                 const float* __restrict__ Wr_h, const float* __restrict__ Wi_h,
                 const float* __restrict__ Wh_h, const float* __restrict__ Wo1,
                 const float* __restrict__ Wo2) {
    int s = blockIdx.x;
    if (s < 8) {
        const float* src = W1 + s * 16384;
        float* dst = g_W1T + s * 128 * SPW;
        for (int t = threadIdx.x; t < 16384; t += 256) {
            int n = t >> 7, f = t & 127;
            dst[n * SPW + f] = src[f * 128 + n];
        }
    } else if (s < 12) {
        const float* src = W2 + (s - 8) * 16384;
        __nv_bfloat16* dst = g_W2T + (s - 8) * 128 * SP;
        for (int t = threadIdx.x; t < 16384; t += 256) {
            int n = t >> 7, f = t & 127;
            dst[n * SP + f] = __float2bfloat16_rn(src[f * 128 + n]);
        }
    } else {
        const float* src;
        switch (s - 12) {
            case 0: src = Wr_h; break;
            case 1: src = Wi_h; break;
            case 2: src = Wh_h; break;
            case 3: src = Wo1;  break;
            default: src = Wo2; break;
        }
        float* dst = g_WnT + (s - 12) * 128 * SPW;
        for (int t = threadIdx.x; t < 16384; t += 256) {
            int h = t >> 7, f = t & 127;
            dst[h * SPW + f] = src[f * 128 + h];
        }
    }
}

// ---------------- UV: tf32 GEMM, M-split (one batch per block), bf16 output ----------------
#define UV_A  0
#define UV_B  UVA_B
#define UV_MB (UVA_B + TILEF_B)
#define UV_SMEM (UV_MB + 32)

__global__ __launch_bounds__(512)
void uv_kernel() {
    extern __shared__ char sm[];
    uint32_t smb = smem_u32(sm);
    int tid = threadIdx.x;
    int ks = blockIdx.x, b = blockIdx.y;   // 8 x 16 = 128 blocks
    uint32_t mbt = smb + UV_MB;
    float* A = (float*)(sm + UV_A);
    const float* Bt = (const float*)(sm + UV_B);

    if (tid == 0) {
        MBAR_INIT(mbt, 1);
        FENCE_ASYNC();
        MBAR_EXPECT_TX(mbt, TILEF_B);
        BULK_CP(smb + UV_B, (const char*)(g_W1T + (size_t)ks * 128 * SPW), TILEF_B, mbt);
    }
    for (int idx = tid; idx < 64 * 32; idx += 512) {
        int row = idx >> 5, f4 = (idx & 31) * 4;
        float4 v = *(const float4*)(g_hidden + ((size_t)(b * NN + row)) * HH + f4);
        *(float4*)&A[row * SPW + f4] = v;
    }
    __syncthreads();
    MBAR_WAIT(mbt, 0);

    int w = tid >> 5, lane = tid & 31;
    int mblk = w & 3, nblk = w >> 2;
    int gid = lane >> 2, tig = lane & 3;

    float acc[4][4];
    #pragma unroll
    for (int nf = 0; nf < 4; nf++)
        #pragma unroll
        for (int j = 0; j < 4; j++) acc[nf][j] = 0.0f;

    gemm_tf32_16(A, Bt, acc, mblk, nblk, lane);
    __syncthreads();

    {
        int r0 = mblk * 16 + gid;
        #pragma unroll
        for (int nf = 0; nf < 4; nf++) {
            int c = nblk * 32 + nf * 8 + tig * 2;
            *(float2*)&A[r0 * SPW + c]       = make_float2(acc[nf][0], acc[nf][1]);
            *(float2*)&A[(r0 + 8) * SPW + c] = make_float2(acc[nf][2], acc[nf][3]);
        }
    }
    __syncthreads();
    for (int idx = tid; idx < 64 * 16; idx += 512) {
        int row = idx >> 4, c8 = (idx & 15) * 8;
        float4 v0 = *(const float4*)&A[row * SPW + c8];
        float4 v1 = *(const float4*)&A[row * SPW + c8 + 4];
        __nv_bfloat162 p0 = __floats2bfloat162_rn(v0.x, v0.y);
        __nv_bfloat162 p1 = __floats2bfloat162_rn(v0.z, v0.w);
        __nv_bfloat162 p2 = __floats2bfloat162_rn(v1.x, v1.y);
        __nv_bfloat162 p3 = __floats2bfloat162_rn(v1.z, v1.w);
        __nv_bfloat162* dst = (__nv_bfloat162*)(g_uv + ((size_t)(b * 8 + ks) * 64 + row) * 128 + c8);
        dst[0] = p0; dst[1] = p1; dst[2] = p2; dst[3] = p3;
    }
}

// ---------------- MSG kernel: one block per (pair, batch, k); 2 CTAs/SM ----------------
#define MS_A    0
#define MS_B    34816
#define MS_U    69632
#define MS_VS   86016
#define MS_SCR  87040
#define MS_REL  89088
#define MS_SEND 89600
#define MS_B2   90112
#define MS_MB   90624
#define MSG_SMEM 90656

__global__ __launch_bounds__(512, 2)
void msg_kernel(const float* __restrict__ b1, const float* __restrict__ b2,
                const float* __restrict__ rel,
                const int* __restrict__ recv_idx, const int* __restrict__ send_idx) {
    extern __shared__ char sm[];
    uint32_t smb = smem_u32(sm);
    int tid = threadIdx.x;
    int p = blockIdx.x, b = blockIdx.y, k = blockIdx.z;

    float* RelS  = (float*)(sm + MS_REL);
    int*   SendS = (int*)(sm + MS_SEND);
    float* b2S   = (float*)(sm + MS_B2);
    float* vS    = (float*)(sm + MS_VS);
    float* scr   = (float*)(sm + MS_SCR);
    uint32_t bbar = smb + MS_MB, ubar = smb + MS_MB + 8;

    if (tid == 0) {
        MBAR_INIT(bbar, 1);
        MBAR_INIT(ubar, 1);
        FENCE_ASYNC();
        MBAR_EXPECT_TX(bbar, TILEH_B);
        BULK_CP(smb + MS_B, (const char*)(g_W2T + (size_t)k * 128 * SP), TILEH_B, bbar);
        MBAR_EXPECT_TX(ubar, 16384);
        BULK_CP(smb + MS_U, (const char*)(g_uv + (size_t)(b * 8 + 2 * k) * 8192), 16384, ubar);
    }
    int r0n = recv_idx[p * 126];
    int r1n = recv_idx[p * 126 + 63];
    if (tid < 128) {
        int row = tid;
        float rw = 0.0f;
        int sn = 0;
        if (row != 63 && row != 127) {
            int e = (row < 64) ? (p * 126 + row) : (p * 126 + row - 1);
            sn = send_idx[e];
            rw = rel[((size_t)(b * EE + e)) * KK + k];
        }
        SendS[row] = sn;
        RelS[row] = rw;
        b2S[row] = b2[k * 128 + row];
    } else if (tid < 384) {
        int f = tid & 127, rh = (tid >> 7) & 1;
        int rv = rh ? r1n : r0n;
        const __nv_bfloat16* v = g_uv + ((size_t)(b * 8 + 2 * k + 1)) * 8192 + rv * 128;
        vS[rh * 128 + f] = __bfloat162float(v[f]) + b1[k * 128 + f];
    }
    __syncthreads();

    // build A = bf16(tanh(u[send] + vS)); rows 63/127 zero (vS cached in registers)
    MBAR_WAIT(ubar, 0);
    {
        const __nv_bfloat16* U = (const __nv_bfloat16*)(sm + MS_U);
        int f4 = (tid & 31) * 4;
        int rowbase = tid >> 5;
        float4 vv0 = *(const float4*)&vS[f4];
        float4 vv1 = *(const float4*)&vS[128 + f4];
        char* Abase = sm + MS_A + f4 * 2;
        #pragma unroll
        for (int it = 0; it < 8; it++) {
            int row = rowbase + 16 * it;
            uint32_t o01 = 0, o23 = 0;
            if (row != 63 && row != 127) {
                int sn = SendS[row];
                float4 vv = (row < 64) ? vv0 : vv1;
                uint2 q = *(const uint2*)(U + sn * 128 + f4);
                float2 f0 = __bfloat1622float2(*(__nv_bfloat162*)&q.x);
                float2 f1 = __bfloat1622float2(*(__nv_bfloat162*)&q.y);
                __nv_bfloat162 p0 = __floats2bfloat162_rn(ftanha_(f0.x + vv.x), ftanha_(f0.y + vv.y));
                __nv_bfloat162 p1 = __floats2bfloat162_rn(ftanha_(f1.x + vv.z), ftanha_(f1.y + vv.w));
                o01 = *(uint32_t*)&p0; o23 = *(uint32_t*)&p1;
            }
            *(uint2*)(Abase + row * SPB) = make_uint2(o01, o23);
        }
    }
    __syncthreads();

    MBAR_WAIT(bbar, 0);
    int w = tid >> 5, lane = tid & 31;
    int mblk = w & 3, nblk = w >> 2;
    int gid = lane >> 2, tig = lane & 3;

    float acc[2][4][4];
    #pragma unroll
    for (int mf = 0; mf < 2; mf++)
        #pragma unroll
        for (int nf = 0; nf < 4; nf++)
            #pragma unroll
            for (int j = 0; j < 4; j++) acc[mf][nf][j] = 0.0f;

    gemm_bf16_ldsm(smb + MS_A, smb + MS_B, acc, mblk, nblk, lane);

    // fused epilogue + row-sum
    float sum[4][2];
    #pragma unroll
    for (int nf = 0; nf < 4; nf++) { sum[nf][0] = 0.0f; sum[nf][1] = 0.0f; }
    {
        int r0 = mblk * 32 + gid;
        float rw0 = RelS[r0];
        float rw1 = RelS[r0 + 8];
        float rw2 = RelS[r0 + 16];
        float rw3 = RelS[r0 + 24];
        #pragma unroll
        for (int nf = 0; nf < 4; nf++) {
            int c = nblk * 32 + nf * 8 + tig * 2;
            float bb0 = b2S[c], bb1 = b2S[c + 1];
            sum[nf][0] += rw0 * ftanha_(acc[0][nf][0] + bb0)
                        + rw1 * ftanha_(acc[0][nf][2] + bb0)
                        + rw2 * ftanha_(acc[1][nf][0] + bb0)
                        + rw3 * ftanha_(acc[1][nf][2] + bb0);
            sum[nf][1] += rw0 * ftanha_(acc[0][nf][1] + bb1)
                        + rw1 * ftanha_(acc[0][nf][3] + bb1)
                        + rw2 * ftanha_(acc[1][nf][1] + bb1)
                        + rw3 * ftanha_(acc[1][nf][3] + bb1);
        }
    }
    #pragma unroll
    for (int off = 16; off >= 4; off >>= 1)
        #pragma unroll
        for (int nf = 0; nf < 4; nf++) {
            sum[nf][0] += __shfl_down_sync(0xffffffffu, sum[nf][0], off);
            sum[nf][1] += __shfl_down_sync(0xffffffffu, sum[nf][1], off);
        }
    if (gid == 0) {
        #pragma unroll
        for (int nf = 0; nf < 4; nf++) {
            int c = nblk * 32 + nf * 8 + tig * 2;
            *(float2*)&scr[mblk * 128 + c] = make_float2(sum[nf][0], sum[nf][1]);
        }
    }
    __syncthreads();
    if (tid < 256) {
        int h = tid & 127, rh = tid >> 7;
        float a = scr[(rh * 2) * 128 + h] + scr[(rh * 2 + 1) * 128 + h];
        int rv = rh ? r1n : r0n;
        g_aggk[(((size_t)k * BB + b) * NN + rv) * HH + h] = a;
    }
}

// ---------------- NODE kernel (weight-register-reuse GEMV) ----------------
#define ND_WB0 0
#define ND_WB1 67584
#define ND_AGG 135168
#define ND_HID 139264
#define ND_T1  143360
#define ND_T2  147456
#define ND_INS 151552
#define ND_WIN 151808
#define ND_BIA 157952
#define ND_WO3 160512
#define ND_BO3 162560
#define ND_MB  162576
#define NODE_SMEM 162640

__global__ __launch_bounds__(256)
void node_kernel(const float* __restrict__ data, int step,
                 const float* __restrict__ Wr_in, const float* __restrict__ br_in,
                 const float* __restrict__ Wi_in, const float* __restrict__ bi_in,
                 const float* __restrict__ Wn_in, const float* __restrict__ bn_in,
                 const float* __restrict__ bo1, const float* __restrict__ bo2,
                 const float* __restrict__ Wo3, const float* __restrict__ bo3,
                 float* __restrict__ out) {
    extern __shared__ char sm[];
    uint32_t smb = smem_u32(sm);
    int q = blockIdx.x, b = blockIdx.y;
    int n0 = q * 8;
    int tid = threadIdx.x;

    float* aggS = (float*)(sm + ND_AGG);
    float* hidS = (float*)(sm + ND_HID);
    float* t1   = (float*)(sm + ND_T1);
    float* t2   = (float*)(sm + ND_T2);
    float* insS = (float*)(sm + ND_INS);
    float* WinS = (float*)(sm + ND_WIN);
    float* biaS = (float*)(sm + ND_BIA);
    float* Wo3S = (float*)(sm + ND_WO3);
    float* bo3S = (float*)(sm + ND_BO3);
    uint32_t mb0 = smb + ND_MB, mb1 = smb + ND_MB + 8;

    if (tid == 0) {
        MBAR_INIT(mb0, 1);
        MBAR_INIT(mb1, 1);
        FENCE_ASYNC();
        MBAR_EXPECT_TX(mb0, TILEF_B);
        BULK_CP(smb + ND_WB0, (const char*)(g_WnT + 0), TILEF_B, mb0);
        MBAR_EXPECT_TX(mb1, TILEF_B);
        BULK_CP(smb + ND_WB1, (const char*)(g_WnT + (size_t)1 * 128 * SPW), TILEF_B, mb1);
    }
    {
        size_t base = ((size_t)(b * NN + n0)) * HH;
        const float4* a0 = (const float4*)(g_aggk + base);
        const float4* a1 = (const float4*)(g_aggk + base + (size_t)BB * NN * HH);
        const float4* a2 = (const float4*)(g_aggk + base + (size_t)2 * BB * NN * HH);
        const float4* a3 = (const float4*)(g_aggk + base + (size_t)3 * BB * NN * HH);
        float4 s0 = a0[tid], s1 = a1[tid], s2 = a2[tid], s3 = a3[tid];
        float4 s;
        s.x = (s0.x + s1.x + s2.x + s3.x) * (1.0f / 16.0f);
        s.y = (s0.y + s1.y + s2.y + s3.y) * (1.0f / 16.0f);
        s.z = (s0.z + s1.z + s2.z + s3.z) * (1.0f / 16.0f);
        s.w = (s0.w + s1.w + s2.w + s3.w) * (1.0f / 16.0f);
        ((float4*)aggS)[tid] = s;
        const float* hg = g_hidden + base;
        ((float4*)hidS)[tid] = ((const float4*)hg)[tid];
    }
    if (tid < 32) {
        int n = tid >> 2, d = tid & 3;
        float v;
        if (step < TT) v = data[(((size_t)(b * NN + n0 + n)) * DD + d) * TT + step];
        else           v = g_pred[(b * NN + n0 + n) * DD + d];
        insS[tid] = v;
    }
    for (int i = tid; i < 512; i += 256) {
        WinS[i]        = Wr_in[i];
        WinS[512 + i]  = Wi_in[i];
        WinS[1024 + i] = Wn_in[i];
        Wo3S[i]        = Wo3[i];
    }
    if (tid < 128) {
        biaS[tid]       = br_in[tid];
        biaS[128 + tid] = bi_in[tid];
        biaS[256 + tid] = bn_in[tid];
        biaS[384 + tid] = bo1[tid];
        biaS[512 + tid] = bo2[tid];
    }
    if (tid < 4) bo3S[tid] = bo3[tid];
    __syncthreads();

    int h = tid & 127, ng = (tid >> 7) * 4;

    // f4-outer GEMV: load each weight float4 ONCE, apply to all 4 node rows
    #define GEMV4(ACT, WB, OUTARR) do { \
        const float4* _wt = (const float4*)(WB) + h * 33; \
        const float4* _a0 = (const float4*)((ACT) + (ng + 0) * 128); \
        const float4* _a1 = (const float4*)((ACT) + (ng + 1) * 128); \
        const float4* _a2 = (const float4*)((ACT) + (ng + 2) * 128); \
        const float4* _a3 = (const float4*)((ACT) + (ng + 3) * 128); \
        float _s0 = 0.0f, _s1 = 0.0f, _s2 = 0.0f, _s3 = 0.0f; \
        _Pragma("unroll 8") \
        for (int f4 = 0; f4 < 32; f4++) { \
            float4 wv = _wt[f4]; \
            float4 x0 = _a0[f4]; \
            _s0 += x0.x * wv.x + x0.y * wv.y + x0.z * wv.z + x0.w * wv.w; \
            float4 x1 = _a1[f4]; \
            _s1 += x1.x * wv.x + x1.y * wv.y + x1.z * wv.z + x1.w * wv.w; \
            float4 x2 = _a2[f4]; \
            _s2 += x2.x * wv.x + x2.y * wv.y + x2.z * wv.z + x2.w * wv.w; \
            float4 x3 = _a3[f4]; \
            _s3 += x3.x * wv.x + x3.y * wv.y + x3.z * wv.z + x3.w * wv.w; \
        } \
        (OUTARR)[0] = _s0; (OUTARR)[1] = _s1; (OUTARR)[2] = _s2; (OUTARR)[3] = _s3; \
    } while (0)

    float acc[4];
    float rr[4], ii[4];

    MBAR_WAIT(mb0, 0);
    GEMV4(aggS, (sm + ND_WB0), acc);
    #pragma unroll
    for (int nn = 0; nn < 4; nn++) {
        int n = ng + nn;
        float a = acc[nn] + biaS[h];
        #pragma unroll
        for (int d = 0; d < 4; d++) a += insS[n*4+d] * WinS[d*128 + h];
        t1[n*128 + h] = fsig_(a);
    }
    __syncthreads();
    if (tid == 0) { MBAR_EXPECT_TX(mb0, TILEF_B); BULK_CP(smb + ND_WB0, (const char*)(g_WnT + (size_t)2 * 128 * SPW), TILEF_B, mb0); }

    MBAR_WAIT(mb1, 0);
    GEMV4(aggS, (sm + ND_WB1), acc);
    #pragma unroll
    for (int nn = 0; nn < 4; nn++) {
        int n = ng + nn;
        float a = acc[nn] + biaS[128 + h];
        #pragma unroll
        for (int d = 0; d < 4; d++) a += insS[n*4+d] * WinS[512 + d*128 + h];
        ii[nn] = fsig_(a);
        rr[nn] = t1[n*128 + h];
    }
    __syncthreads();
    if (tid == 0) { MBAR_EXPECT_TX(mb1, TILEF_B); BULK_CP(smb + ND_WB1, (const char*)(g_WnT + (size_t)3 * 128 * SPW), TILEF_B, mb1); }

    MBAR_WAIT(mb0, 1);
    GEMV4(aggS, (sm + ND_WB0), acc);
    #pragma unroll
    for (int nn = 0; nn < 4; nn++) {
        int n = ng + nn;
        float a = biaS[256 + h];
        #pragma unroll
        for (int d = 0; d < 4; d++) a += insS[n*4+d] * WinS[1024 + d*128 + h];
        float nv = ftanh_(a + rr[nn] * acc[nn]);
        float hn = (1.0f - ii[nn]) * nv + ii[nn] * hidS[n*128 + h];
        hidS[n*128 + h] = hn;
        g_hidden[((size_t)(b * NN + n0 + n)) * HH + h] = hn;
    }
    __syncthreads();
    if (tid == 0) { MBAR_EXPECT_TX(mb0, TILEF_B); BULK_CP(smb + ND_WB0, (const char*)(g_WnT + (size_t)4 * 128 * SPW), TILEF_B, mb0); }

    MBAR_WAIT(mb1, 1);
    GEMV4(hidS, (sm + ND_WB1), acc);
    #pragma unroll
    for (int nn = 0; nn < 4; nn++)
        t1[(ng+nn)*128 + h] = fmaxf(acc[nn] + biaS[384 + h], 0.0f);
    __syncthreads();

    MBAR_WAIT(mb0, 0);
    GEMV4(t1, (sm + ND_WB0), acc);
    #pragma unroll
    for (int nn = 0; nn < 4; nn++)
        t2[(ng+nn)*128 + h] = fmaxf(acc[nn] + biaS[512 + h], 0.0f);
    __syncthreads();

    if (tid < 32) {
        int n = tid >> 2, d = tid & 3;
        float a = bo3S[d];
        const float* vv = t2 + n*128;
        #pragma unroll 8
        for (int hh = 0; hh < 128; hh++) a += vv[hh] * Wo3S[hh*4 + d];
        float pred = insS[tid] + a;
        g_pred[(b * NN + n0 + n) * DD + d] = pred;
        if (step >= TT)
            out[(((size_t)(b * NN + n0 + n)) * DD + d) * LL + (step - TT)] = pred;
    }
    #undef GEMV4
}

// ---------------- launch ----------------
extern "C" void kernel_launch(void* const* d_in, const int* in_sizes, int n_in,
                              void* d_out, int out_size) {
    const float* data  = (const float*)d_in[0];
    const float* rel   = (const float*)d_in[1];
    const float* W1    = (const float*)d_in[2];
    const float* b1    = (const float*)d_in[3];
    const float* W2    = (const float*)d_in[4];
    const float* b2    = (const float*)d_in[5];
    const float* Wr_h  = (const float*)d_in[6];
    const float* Wi_h  = (const float*)d_in[7];
    const float* Wh_h  = (const float*)d_in[8];
    const float* Wr_in = (const float*)d_in[9];
    const float* br_in = (const float*)d_in[10];
    const float* Wi_in = (const float*)d_in[11];
    const float* bi_in = (const float*)d_in[12];
    const float* Wn_in = (const float*)d_in[13];
    const float* bn_in = (const float*)d_in[14];
    const float* Wo1   = (const float*)d_in[15];
    const float* bo1   = (const float*)d_in[16];
    const float* Wo2   = (const float*)d_in[17];
    const float* bo2   = (const float*)d_in[18];
    const float* Wo3   = (const float*)d_in[19];
    const float* bo3   = (const float*)d_in[20];
    const int* recv_idx = (const int*)d_in[21];
    const int* send_idx = (const int*)d_in[22];
    float* out = (float*)d_out;

    cudaFuncSetAttribute(uv_kernel,   cudaFuncAttributeMaxDynamicSharedMemorySize, UV_SMEM);
    cudaFuncSetAttribute(msg_kernel,  cudaFuncAttributeMaxDynamicSharedMemorySize, MSG_SMEM);
    cudaFuncSetAttribute(node_kernel, cudaFuncAttributeMaxDynamicSharedMemorySize, NODE_SMEM);

    init_kernel<<<512, 256>>>();
    prep_kernel<<<17, 256>>>(W1, W2, Wr_h, Wi_h, Wh_h, Wo1, Wo2);
    for (int s = 0; s < TT + LL; s++) {
        uv_kernel<<<dim3(8, 16), 512, UV_SMEM>>>();
        msg_kernel<<<dim3(32, BB, KK), 512, MSG_SMEM>>>(b1, b2, rel, recv_idx, send_idx);
        node_kernel<<<dim3(8, BB), 256, NODE_SMEM>>>(data, s,
            Wr_in, br_in, Wi_in, bi_in, Wn_in, bn_in,
            bo1, bo2, Wo3, bo3, out);
    }
}